// round 2
// baseline (speedup 1.0000x reference)
#include <cuda_runtime.h>
#include <cuda_fp16.h>
#include <cstdint>

// ============================================================================
// Problem sizes
// ============================================================================
static constexpr int NVOX  = 65536;
static constexpr int CIN   = 64;
static constexpr int CH    = 64;
static constexpr int COUT3 = 16;
static constexpr int KOFF  = 27;
static constexpr int TM    = 128;            // voxel rows per CTA tile
static constexpr int NTILE = NVOX / TM;      // 512

// ============================================================================
// Device scratch (no dynamic allocation allowed)
// ============================================================================
__device__ __half g_xh[NVOX * CIN];
__device__ __half g_h1[NVOX * CH];
__device__ __half g_h2[NVOX * CH];
// weights pre-packed in mma.m16n8k16 B-fragment order:
// [k][ko][no][lane] -> uint2 (4 halves)
__device__ __half g_W1f[KOFF * CH * CIN];
__device__ __half g_W2f[KOFF * CH * CH];
__device__ __half g_W3f[KOFF * COUT3 * CH];

// ============================================================================
// PTX helpers (portable sm_100 subset: cp.async + ldmatrix + mma.sync)
// ============================================================================
__device__ __forceinline__ uint32_t smem_to_u32(const void* smem_ptr) {
    uint32_t addr;
    asm("{ .reg .u64 tmp; cvta.to.shared.u64 tmp, %1; cvt.u32.u64 %0, tmp; }"
        : "=r"(addr) : "l"(smem_ptr));
    return addr;
}

__device__ __forceinline__ void cp_async16(uint32_t dst, const void* src,
                                           uint32_t src_size) {
    asm volatile("cp.async.cg.shared.global [%0], [%1], 16, %2;"
                 :: "r"(dst), "l"(src), "r"(src_size));
}
__device__ __forceinline__ void cp_commit() {
    asm volatile("cp.async.commit_group;");
}
template <int N>
__device__ __forceinline__ void cp_wait() {
    asm volatile("cp.async.wait_group %0;" :: "n"(N));
}

__device__ __forceinline__ void ldmatrix_x4(uint32_t* a, uint32_t addr) {
    asm volatile("ldmatrix.sync.aligned.m8n8.x4.shared.b16 {%0,%1,%2,%3}, [%4];"
                 : "=r"(a[0]), "=r"(a[1]), "=r"(a[2]), "=r"(a[3]) : "r"(addr));
}

__device__ __forceinline__ void mma16816(float* c, const uint32_t* a,
                                         const uint32_t* b) {
    asm volatile(
        "mma.sync.aligned.m16n8k16.row.col.f32.f16.f16.f32 "
        "{%0,%1,%2,%3}, {%4,%5,%6,%7}, {%8,%9}, {%0,%1,%2,%3};"
        : "+f"(c[0]), "+f"(c[1]), "+f"(c[2]), "+f"(c[3])
        : "r"(a[0]), "r"(a[1]), "r"(a[2]), "r"(a[3]), "r"(b[0]), "r"(b[1]));
}

// ============================================================================
// SMEM layout (bytes, within dynamic smem)
// ============================================================================
static constexpr int SMEM_IDX = 0;                      // 27*128*4 = 13824
static constexpr int SMEM_A   = 14336;                  // 2 x 16384 (128-row fp16 tiles)
static constexpr int A_BYTES  = TM * 128;
static constexpr int SMEM_B   = SMEM_A + 2 * A_BYTES;   // 47104; 2 x (COUT*128)

// ============================================================================
// One sparse-conv layer: out[n,:] = act( sum_k feat[nidx[n,k],:] @ W[k] + b )
// 4 warps per CTA, each warp: m32 x nCOUT, fp32 accum in registers.
// ============================================================================
template <int COUT, bool RELU, typename OUT_T>
__global__ void __launch_bounds__(128)
layer_kernel(const __half* __restrict__ feat,
             const int*    __restrict__ nidx,
             const __half* __restrict__ Wf,
             const float*  __restrict__ bias,
             OUT_T*        __restrict__ out)
{
    constexpr int NO      = COUT / 8;        // n8 tiles per warp
    constexpr int B_BYTES = COUT * 128;      // 64 (k) * COUT * 2B per offset
    extern __shared__ char smem[];
    const uint32_t smem_base = smem_to_u32(smem);
    const int tid  = threadIdx.x;
    const int wid  = tid >> 5;
    const int lane = tid & 31;
    const int base_row = blockIdx.x * TM;

    // ---- stage neighbor indices, transposed to [k][row] for per-k access ----
    int* s_idx = (int*)(smem + SMEM_IDX);
    {
        const int* src = nidx + base_row * KOFF;
        for (int i = tid; i < TM * KOFF; i += 128) {
            int r = i / KOFF, k = i - r * KOFF;
            s_idx[k * TM + r] = src[i];
        }
    }
    __syncthreads();

    const char* bsrc_base = (const char*)Wf;

    // ---- gather stage for offset k into buffer buf ----
    auto stage = [&](int k, int buf) {
        // A: thread t gathers row t (128B = 8 x 16B chunks, XOR-16B swizzle)
        int nb = s_idx[k * TM + tid];
        uint32_t ss = (nb >= 0) ? 16u : 0u;
        const char* src = (const char*)(feat + (size_t)max(nb, 0) * 64);
        uint32_t drow = smem_base + SMEM_A + buf * A_BYTES + tid * 128;
        uint32_t sw = (uint32_t)(tid & 7) * 16;
        #pragma unroll
        for (int c = 0; c < 8; c++)
            cp_async16(drow + (((uint32_t)(c * 16)) ^ sw), src + c * 16, ss);
        // B: linear copy of this offset's fragment-ordered weight tile
        const char* bs = bsrc_base + (size_t)k * B_BYTES;
        uint32_t bd = smem_base + SMEM_B + buf * B_BYTES;
        #pragma unroll
        for (int j = 0; j < B_BYTES / 2048; j++) {
            int idx = j * 128 + tid;
            cp_async16(bd + idx * 16, bs + idx * 16, 16);
        }
        cp_commit();
    };

    float acc[2][NO][4];
    #pragma unroll
    for (int mt = 0; mt < 2; mt++)
        #pragma unroll
        for (int no = 0; no < NO; no++)
            #pragma unroll
            for (int r = 0; r < 4; r++)
                acc[mt][no][r] = 0.f;

    stage(0, 0);

    const int m0 = wid * 32;
    for (int k = 0; k < KOFF; k++) {
        const int buf = k & 1;
        if (k + 1 < KOFF) { stage(k + 1, (k + 1) & 1); cp_wait<1>(); }
        else              { cp_wait<0>(); }
        __syncthreads();

        const uint32_t aBase = smem_base + SMEM_A + buf * A_BYTES;
        const uint32_t bBase = smem_base + SMEM_B + buf * B_BYTES;
        #pragma unroll
        for (int ko = 0; ko < 4; ko++) {
            uint32_t afrag[2][4];
            #pragma unroll
            for (int mt = 0; mt < 2; mt++) {
                int r  = m0 + mt * 16 + (lane & 15);
                int ch = ko * 2 + (lane >> 4);
                uint32_t addr = aBase + r * 128 + (((uint32_t)ch ^ (uint32_t)(r & 7)) * 16);
                ldmatrix_x4(afrag[mt], addr);
            }
            #pragma unroll
            for (int no = 0; no < NO; no++) {
                uint32_t b[2];
                asm volatile("ld.shared.v2.b32 {%0,%1}, [%2];"
                             : "=r"(b[0]), "=r"(b[1])
                             : "r"(bBase + ((ko * NO + no) * 32 + lane) * 8));
                mma16816(acc[0][no], afrag[0], b);
                mma16816(acc[1][no], afrag[1], b);
            }
        }
        __syncthreads();
    }

    // ---- epilogue: +bias, activation, store ----
    float2 bb[NO];
    #pragma unroll
    for (int no = 0; no < NO; no++) {
        int c0 = no * 8 + (lane & 3) * 2;
        bb[no].x = bias[c0];
        bb[no].y = bias[c0 + 1];
    }
    #pragma unroll
    for (int mt = 0; mt < 2; mt++) {
        int r0 = base_row + m0 + mt * 16 + (lane >> 2);
        #pragma unroll
        for (int no = 0; no < NO; no++) {
            int c0 = no * 8 + (lane & 3) * 2;
            float f0 = acc[mt][no][0] + bb[no].x;
            float f1 = acc[mt][no][1] + bb[no].y;
            float f2 = acc[mt][no][2] + bb[no].x;
            float f3 = acc[mt][no][3] + bb[no].y;
            if (RELU) {
                f0 = fmaxf(f0, 0.f); f1 = fmaxf(f1, 0.f);
                f2 = fmaxf(f2, 0.f); f3 = fmaxf(f3, 0.f);
            }
            if constexpr (sizeof(OUT_T) == 2) {
                __half2* o0 = (__half2*)((__half*)out + (size_t)r0 * COUT + c0);
                __half2* o1 = (__half2*)((__half*)out + (size_t)(r0 + 8) * COUT + c0);
                *o0 = __floats2half2_rn(f0, f1);
                *o1 = __floats2half2_rn(f2, f3);
            } else {
                float2* o0 = (float2*)((float*)out + (size_t)r0 * COUT + c0);
                float2* o1 = (float2*)((float*)out + (size_t)(r0 + 8) * COUT + c0);
                *o0 = make_float2(f0, f1);
                *o1 = make_float2(f2, f3);
            }
        }
    }
}

// ============================================================================
// Prologue kernels
// ============================================================================
__global__ void k_cvt_x(const float* __restrict__ x, __half* __restrict__ xh,
                        int npairs) {
    int i = blockIdx.x * blockDim.x + threadIdx.x;
    if (i < npairs) {
        float2 v = ((const float2*)x)[i];
        ((__half2*)xh)[i] = __floats2half2_rn(v.x, v.y);
    }
}

// Pack W[k][kk][n] (fp32, kk = contraction 0..63, n = 0..Cout-1) into
// mma.m16n8k16 B-fragment order: [k][ko][no][lane] -> uint2 of 4 halves
//   .x = (B[kk0][n], B[kk0+1][n])   .y = (B[kk0+8][n], B[kk0+9][n])
//   kk0 = ko*16 + (lane%4)*2,  n = no*8 + lane/4
__global__ void k_prep_b(const float* __restrict__ W, __half* __restrict__ Bf,
                         int Cout) {
    int NOv = Cout / 8;
    int tot = KOFF * 4 * NOv * 32;
    int i = blockIdx.x * blockDim.x + threadIdx.x;
    if (i >= tot) return;
    int lane = i & 31;
    int g    = i >> 5;
    int no   = g % NOv;
    int ko   = (g / NOv) % 4;
    int k    = g / (NOv * 4);
    int n    = no * 8 + (lane >> 2);
    int kk0  = ko * 16 + (lane & 3) * 2;
    const float* Wk = W + (size_t)k * 64 * Cout;
    __half h0 = __float2half_rn(Wk[(kk0 + 0) * Cout + n]);
    __half h1 = __float2half_rn(Wk[(kk0 + 1) * Cout + n]);
    __half h2 = __float2half_rn(Wk[(kk0 + 8) * Cout + n]);
    __half h3 = __float2half_rn(Wk[(kk0 + 9) * Cout + n]);
    uint2 v;
    v.x = (uint32_t)__half_as_ushort(h0) | ((uint32_t)__half_as_ushort(h1) << 16);
    v.y = (uint32_t)__half_as_ushort(h2) | ((uint32_t)__half_as_ushort(h3) << 16);
    ((uint2*)Bf)[i] = v;
}

// ============================================================================
// kernel_launch
// ============================================================================
extern "C" void kernel_launch(void* const* d_in, const int* in_sizes, int n_in,
                              void* d_out, int out_size) {
    const float* x    = (const float*)d_in[0];
    const int*   nidx = (const int*)  d_in[1];
    const float* W1   = (const float*)d_in[2];
    const float* b1   = (const float*)d_in[3];
    const float* W2   = (const float*)d_in[4];
    const float* b2   = (const float*)d_in[5];
    const float* W3   = (const float*)d_in[6];
    const float* b3   = (const float*)d_in[7];

    __half *xh, *h1, *h2, *w1f, *w2f, *w3f;
    cudaGetSymbolAddress((void**)&xh,  g_xh);
    cudaGetSymbolAddress((void**)&h1,  g_h1);
    cudaGetSymbolAddress((void**)&h2,  g_h2);
    cudaGetSymbolAddress((void**)&w1f, g_W1f);
    cudaGetSymbolAddress((void**)&w2f, g_W2f);
    cudaGetSymbolAddress((void**)&w3f, g_W3f);

    constexpr int SZ64 = SMEM_B + 2 * 64 * 128;  // 63488
    constexpr int SZ16 = SMEM_B + 2 * 16 * 128;  // 51200
    cudaFuncSetAttribute((const void*)layer_kernel<64, true,  __half>,
                         cudaFuncAttributeMaxDynamicSharedMemorySize, SZ64);
    cudaFuncSetAttribute((const void*)layer_kernel<16, false, float>,
                         cudaFuncAttributeMaxDynamicSharedMemorySize, SZ16);

    // prologue: fp16 convert + weight fragment packing
    {
        int npairs = NVOX * CIN / 2;
        k_cvt_x<<<(npairs + 255) / 256, 256>>>(x, xh, npairs);
        int t12 = KOFF * 4 * (64 / 8) * 32;
        k_prep_b<<<(t12 + 255) / 256, 256>>>(W1, w1f, 64);
        k_prep_b<<<(t12 + 255) / 256, 256>>>(W2, w2f, 64);
        int t3 = KOFF * 4 * (16 / 8) * 32;
        k_prep_b<<<(t3 + 255) / 256, 256>>>(W3, w3f, 16);
    }

    layer_kernel<64, true,  __half><<<NTILE, 128, SZ64>>>(xh, nidx, w1f, b1, h1);
    layer_kernel<64, true,  __half><<<NTILE, 128, SZ64>>>(h1, nidx, w2f, b2, h2);
    layer_kernel<16, false, float ><<<NTILE, 128, SZ16>>>(h2, nidx, w3f, b3,
                                                          (float*)d_out);
}

// round 3
// speedup vs baseline: 1.0726x; 1.0726x over previous
#include <cuda_runtime.h>
#include <cuda_fp16.h>
#include <cstdint>

// ============================================================================
// Problem sizes
// ============================================================================
static constexpr int NVOX  = 65536;
static constexpr int CIN   = 64;
static constexpr int CH    = 64;
static constexpr int COUT3 = 16;
static constexpr int KOFF  = 27;
static constexpr int TM    = 256;            // voxel rows per CTA tile
static constexpr int NTILE = NVOX / TM;      // 256
static constexpr int NGRP  = TM / 16;        // 16 m16 groups per tile

// ============================================================================
// Device scratch (no dynamic allocation allowed)
// ============================================================================
__device__ __half g_xh[NVOX * CIN];
__device__ __half g_h1[NVOX * CH];
__device__ __half g_h2[NVOX * CH];
// weights pre-packed in mma.m16n8k16 B-fragment order:
// [k][ko][no][lane] -> uint2 (4 halves)
__device__ __half g_W1f[KOFF * CH * CIN];
__device__ __half g_W2f[KOFF * CH * CH];
__device__ __half g_W3f[KOFF * COUT3 * CH];

// ============================================================================
// PTX helpers (portable sm_100 subset: cp.async + ldmatrix + mma.sync)
// ============================================================================
__device__ __forceinline__ uint32_t smem_to_u32(const void* smem_ptr) {
    uint32_t addr;
    asm("{ .reg .u64 tmp; cvta.to.shared.u64 tmp, %1; cvt.u32.u64 %0, tmp; }"
        : "=r"(addr) : "l"(smem_ptr));
    return addr;
}

__device__ __forceinline__ void cp_async16(uint32_t dst, const void* src,
                                           uint32_t src_size) {
    asm volatile("cp.async.cg.shared.global [%0], [%1], 16, %2;"
                 :: "r"(dst), "l"(src), "r"(src_size));
}
__device__ __forceinline__ void cp_commit() {
    asm volatile("cp.async.commit_group;");
}
template <int N>
__device__ __forceinline__ void cp_wait() {
    asm volatile("cp.async.wait_group %0;" :: "n"(N));
}

__device__ __forceinline__ void ldmatrix_x4(uint32_t* a, uint32_t addr) {
    asm volatile("ldmatrix.sync.aligned.m8n8.x4.shared.b16 {%0,%1,%2,%3}, [%4];"
                 : "=r"(a[0]), "=r"(a[1]), "=r"(a[2]), "=r"(a[3]) : "r"(addr));
}

__device__ __forceinline__ void mma16816(float* c, const uint32_t* a,
                                         const uint32_t* b) {
    asm volatile(
        "mma.sync.aligned.m16n8k16.row.col.f32.f16.f16.f32 "
        "{%0,%1,%2,%3}, {%4,%5,%6,%7}, {%8,%9}, {%0,%1,%2,%3};"
        : "+f"(c[0]), "+f"(c[1]), "+f"(c[2]), "+f"(c[3])
        : "r"(a[0]), "r"(a[1]), "r"(a[2]), "r"(a[3]), "r"(b[0]), "r"(b[1]));
}

// ============================================================================
// SMEM layout (bytes, within dynamic smem)
// ============================================================================
static constexpr int SMEM_MASK = 0;                       // NGRP u32 (+pad)
static constexpr int SMEM_IDX  = 128;                     // 27*256*4 = 27648
static constexpr int SMEM_A    = 28672;                   // 1024-aligned
static constexpr int A_BYTES   = TM * 128;                // 32768
static constexpr int SMEM_B    = SMEM_A + 2 * A_BYTES;    // 94208
// total = SMEM_B + 2*COUT*128

// ============================================================================
// One sparse-conv layer: out[n,:] = act( sum_k feat[nidx[n,k],:] @ W[k] + b )
// 8 warps per CTA, each warp: m32 x nCOUT, fp32 accum in registers.
// Per-(m16 group, k) validity masks skip ~29% of gather+MMA slabs.
// ============================================================================
template <int COUT, bool RELU, typename OUT_T>
__global__ void __launch_bounds__(256, 2)
layer_kernel(const __half* __restrict__ feat,
             const int*    __restrict__ nidx,
             const __half* __restrict__ Wf,
             const float*  __restrict__ bias,
             OUT_T*        __restrict__ out)
{
    constexpr int NO      = COUT / 8;        // n8 tiles per warp
    constexpr int B_BYTES = COUT * 128;      // 64(k) * COUT * 2B per offset
    extern __shared__ char smem[];
    const uint32_t smem_base = smem_to_u32(smem);
    const int tid  = threadIdx.x;
    const int wid  = tid >> 5;
    const int lane = tid & 31;
    const int base_row = blockIdx.x * TM;

    int*      s_idx  = (int*)(smem + SMEM_IDX);
    uint32_t* s_mask = (uint32_t*)(smem + SMEM_MASK);

    if (tid < NGRP) s_mask[tid] = 0u;
    __syncthreads();

    // ---- stage neighbor indices (transposed to [k][row]) + validity masks ----
    {
        const int* ip = nidx + (size_t)(base_row + tid) * KOFF;
        uint32_t m = 0;
        #pragma unroll
        for (int kk = 0; kk < KOFF; kk++) {
            int nb = ip[kk];
            s_idx[kk * TM + tid] = nb;
            m |= (uint32_t)(nb >= 0) << kk;
        }
        atomicOr((int*)&s_mask[tid >> 4], (int)m);
    }
    __syncthreads();

    const char* bsrc_base = (const char*)Wf;

    // ---- gather stage for offset k into buffer buf ----
    auto stage = [&](int k, int buf) {
        // A: thread t gathers row t (128B = 8 x 16B chunks, XOR-16B swizzle),
        // skipped entirely when this thread's m16 group has no valid row at k.
        if ((s_mask[tid >> 4] >> k) & 1u) {
            int nb = s_idx[k * TM + tid];
            uint32_t ss = (nb >= 0) ? 16u : 0u;
            const char* src = (const char*)(feat + (size_t)max(nb, 0) * 64);
            uint32_t drow = smem_base + SMEM_A + buf * A_BYTES + tid * 128;
            uint32_t sw = (uint32_t)(tid & 7) * 16;
            #pragma unroll
            for (int c = 0; c < 8; c++)
                cp_async16(drow + (((uint32_t)(c * 16)) ^ sw), src + c * 16, ss);
        }
        // B: linear copy of this offset's fragment-ordered weight tile
        {
            const char* bs = bsrc_base + (size_t)k * B_BYTES;
            uint32_t bd = smem_base + SMEM_B + buf * B_BYTES;
            #pragma unroll
            for (int j = tid; j < B_BYTES / 16; j += 256)
                cp_async16(bd + j * 16, bs + (size_t)j * 16, 16);
        }
        cp_commit();
    };

    float acc[2][NO][4];
    #pragma unroll
    for (int mt = 0; mt < 2; mt++)
        #pragma unroll
        for (int no = 0; no < NO; no++)
            #pragma unroll
            for (int r = 0; r < 4; r++)
                acc[mt][no][r] = 0.f;

    stage(0, 0);

    const int m0 = wid * 32;
    for (int k = 0; k < KOFF; k++) {
        const int buf = k & 1;
        if (k + 1 < KOFF) { stage(k + 1, buf ^ 1); cp_wait<1>(); }
        else              { cp_wait<0>(); }
        __syncthreads();

        const uint32_t v0 = (s_mask[2 * wid]     >> k) & 1u;
        const uint32_t v1 = (s_mask[2 * wid + 1] >> k) & 1u;
        if (v0 | v1) {
            const uint32_t aBase = smem_base + SMEM_A + buf * A_BYTES;
            const uint32_t bBase = smem_base + SMEM_B + buf * B_BYTES;
            #pragma unroll
            for (int ko = 0; ko < 4; ko++) {
                uint32_t afrag[2][4];
                const int ch = ko * 2 + (lane >> 4);
                if (v0) {
                    int r = m0 + (lane & 15);
                    ldmatrix_x4(afrag[0],
                        aBase + r * 128 + (((uint32_t)ch ^ (uint32_t)(r & 7)) * 16));
                }
                if (v1) {
                    int r = m0 + 16 + (lane & 15);
                    ldmatrix_x4(afrag[1],
                        aBase + r * 128 + (((uint32_t)ch ^ (uint32_t)(r & 7)) * 16));
                }
                #pragma unroll
                for (int no = 0; no < NO; no++) {
                    uint32_t b[2];
                    asm volatile("ld.shared.v2.b32 {%0,%1}, [%2];"
                                 : "=r"(b[0]), "=r"(b[1])
                                 : "r"(bBase + ((ko * NO + no) * 32 + lane) * 8));
                    if (v0) mma16816(acc[0][no], afrag[0], b);
                    if (v1) mma16816(acc[1][no], afrag[1], b);
                }
            }
        }
        __syncthreads();
    }

    // ---- epilogue: +bias, activation, store ----
    float2 bb[NO];
    #pragma unroll
    for (int no = 0; no < NO; no++) {
        int c0 = no * 8 + (lane & 3) * 2;
        bb[no].x = bias[c0];
        bb[no].y = bias[c0 + 1];
    }
    #pragma unroll
    for (int mt = 0; mt < 2; mt++) {
        int r0 = base_row + m0 + mt * 16 + (lane >> 2);
        #pragma unroll
        for (int no = 0; no < NO; no++) {
            int c0 = no * 8 + (lane & 3) * 2;
            float f0 = acc[mt][no][0] + bb[no].x;
            float f1 = acc[mt][no][1] + bb[no].y;
            float f2 = acc[mt][no][2] + bb[no].x;
            float f3 = acc[mt][no][3] + bb[no].y;
            if (RELU) {
                f0 = fmaxf(f0, 0.f); f1 = fmaxf(f1, 0.f);
                f2 = fmaxf(f2, 0.f); f3 = fmaxf(f3, 0.f);
            }
            if constexpr (sizeof(OUT_T) == 2) {
                __half2* o0 = (__half2*)((__half*)out + (size_t)r0 * COUT + c0);
                __half2* o1 = (__half2*)((__half*)out + (size_t)(r0 + 8) * COUT + c0);
                *o0 = __floats2half2_rn(f0, f1);
                *o1 = __floats2half2_rn(f2, f3);
            } else {
                float2* o0 = (float2*)((float*)out + (size_t)r0 * COUT + c0);
                float2* o1 = (float2*)((float*)out + (size_t)(r0 + 8) * COUT + c0);
                *o0 = make_float2(f0, f1);
                *o1 = make_float2(f2, f3);
            }
        }
    }
}

// ============================================================================
// Fused prologue: x -> fp16, and W1/W2/W3 -> mma B-fragment order
//   fragment task i: [k][ko][no][lane] -> uint2 of 4 halves
//     .x = (B[kk0][n], B[kk0+1][n])   .y = (B[kk0+8][n], B[kk0+9][n])
//     kk0 = ko*16 + (lane%4)*2,  n = no*8 + lane/4
// ============================================================================
__device__ __forceinline__ void prep_b_elem(const float* __restrict__ W,
                                            __half* __restrict__ Bf,
                                            int Cout, int i) {
    int NOv  = Cout / 8;
    int lane = i & 31;
    int g    = i >> 5;
    int no   = g % NOv;
    int ko   = (g / NOv) % 4;
    int k    = g / (NOv * 4);
    int n    = no * 8 + (lane >> 2);
    int kk0  = ko * 16 + (lane & 3) * 2;
    const float* Wk = W + (size_t)k * 64 * Cout;
    __half h0 = __float2half_rn(Wk[(kk0 + 0) * Cout + n]);
    __half h1 = __float2half_rn(Wk[(kk0 + 1) * Cout + n]);
    __half h2 = __float2half_rn(Wk[(kk0 + 8) * Cout + n]);
    __half h3 = __float2half_rn(Wk[(kk0 + 9) * Cout + n]);
    uint2 v;
    v.x = (uint32_t)__half_as_ushort(h0) | ((uint32_t)__half_as_ushort(h1) << 16);
    v.y = (uint32_t)__half_as_ushort(h2) | ((uint32_t)__half_as_ushort(h3) << 16);
    ((uint2*)Bf)[i] = v;
}

static constexpr int PREP_NP  = NVOX * CIN / 2;        // x half2 pairs
static constexpr int PREP_T12 = KOFF * 4 * 8 * 32;     // W1/W2 frag tasks
static constexpr int PREP_T3  = KOFF * 4 * 2 * 32;     // W3 frag tasks
static constexpr int PREP_TOT = PREP_NP + 2 * PREP_T12 + PREP_T3;

__global__ void k_prep(const float* __restrict__ x, __half* __restrict__ xh,
                       const float* __restrict__ W1, __half* __restrict__ w1f,
                       const float* __restrict__ W2, __half* __restrict__ w2f,
                       const float* __restrict__ W3, __half* __restrict__ w3f) {
    int i = blockIdx.x * blockDim.x + threadIdx.x;
    if (i < PREP_NP) {
        float2 v = ((const float2*)x)[i];
        ((__half2*)xh)[i] = __floats2half2_rn(v.x, v.y);
    } else if (i < PREP_NP + PREP_T12) {
        prep_b_elem(W1, w1f, 64, i - PREP_NP);
    } else if (i < PREP_NP + 2 * PREP_T12) {
        prep_b_elem(W2, w2f, 64, i - PREP_NP - PREP_T12);
    } else if (i < PREP_TOT) {
        prep_b_elem(W3, w3f, 16, i - PREP_NP - 2 * PREP_T12);
    }
}

// ============================================================================
// kernel_launch
// ============================================================================
extern "C" void kernel_launch(void* const* d_in, const int* in_sizes, int n_in,
                              void* d_out, int out_size) {
    const float* x    = (const float*)d_in[0];
    const int*   nidx = (const int*)  d_in[1];
    const float* W1   = (const float*)d_in[2];
    const float* b1   = (const float*)d_in[3];
    const float* W2   = (const float*)d_in[4];
    const float* b2   = (const float*)d_in[5];
    const float* W3   = (const float*)d_in[6];
    const float* b3   = (const float*)d_in[7];

    __half *xh, *h1, *h2, *w1f, *w2f, *w3f;
    cudaGetSymbolAddress((void**)&xh,  g_xh);
    cudaGetSymbolAddress((void**)&h1,  g_h1);
    cudaGetSymbolAddress((void**)&h2,  g_h2);
    cudaGetSymbolAddress((void**)&w1f, g_W1f);
    cudaGetSymbolAddress((void**)&w2f, g_W2f);
    cudaGetSymbolAddress((void**)&w3f, g_W3f);

    constexpr int SZ64 = SMEM_B + 2 * 64 * 128;  // 110592
    constexpr int SZ16 = SMEM_B + 2 * 16 * 128;  // 98304
    cudaFuncSetAttribute((const void*)layer_kernel<64, true,  __half>,
                         cudaFuncAttributeMaxDynamicSharedMemorySize, SZ64);
    cudaFuncSetAttribute((const void*)layer_kernel<16, false, float>,
                         cudaFuncAttributeMaxDynamicSharedMemorySize, SZ16);

    k_prep<<<(PREP_TOT + 255) / 256, 256>>>(x, xh, W1, w1f, W2, w2f, W3, w3f);

    layer_kernel<64, true,  __half><<<NTILE, 256, SZ64>>>(xh, nidx, w1f, b1, h1);
    layer_kernel<64, true,  __half><<<NTILE, 256, SZ64>>>(h1, nidx, w2f, b2, h2);
    layer_kernel<16, false, float ><<<NTILE, 256, SZ16>>>(h2, nidx, w3f, b3,
                                                          (float*)d_out);
}